// round 2
// baseline (speedup 1.0000x reference)
#include <cuda_runtime.h>
#include <math.h>

#define BATCH 512
#define SEQ   256
#define D     64
#define H     512
#define G     2048   /* 4*H gate columns */
#define KDIM  576    /* D + H */
#define PRED  24

// ---------------- device scratch (no allocations allowed) ----------------
__device__ float g_W[KDIM * G];     // combined weights, [k][g'] with g' = hh*4 + t
__device__ float g_bias[G];         // permuted combined bias
__device__ float g_h[2][BATCH * H]; // ping-pong hidden state
__device__ float g_c[2][BATCH * H]; // ping-pong cell state
__device__ float g_xatt[BATCH * D]; // attention-gated input for current step

__device__ __forceinline__ float sigf(float x) { return 1.0f / (1.0f + expf(-x)); }

// ---------------- init: transpose/permute weights, zero state ----------------
// g' = hh*4 + t  (t: 0=i,1=f,2=g,3=o), original gate row g = t*H + hh.
// g_W[k][g'] = (k < D) ? W_ih[g][k] : W_hh[g][k-D]
__global__ void __launch_bounds__(256) init_kernel(const float* __restrict__ W_ih,
                                                   const float* __restrict__ W_hh,
                                                   const float* __restrict__ b_ih,
                                                   const float* __restrict__ b_hh) {
    const int stride = gridDim.x * blockDim.x;
    const int tid0 = blockIdx.x * blockDim.x + threadIdx.x;

    for (int idx = tid0; idx < KDIM * G; idx += stride) {
        int k  = idx / G;
        int gp = idx - k * G;
        int hh = gp >> 2;
        int t  = gp & 3;
        int g  = t * H + hh;
        float v = (k < D) ? W_ih[g * D + k] : W_hh[g * H + (k - D)];
        g_W[idx] = v;
    }
    for (int idx = tid0; idx < G; idx += stride) {
        int hh = idx >> 2;
        int t  = idx & 3;
        int g  = t * H + hh;
        g_bias[idx] = b_ih[g] + b_hh[g];
    }
    // zero the step-0 input buffers (replay-deterministic re-init)
    for (int idx = tid0; idx < BATCH * H; idx += stride) {
        g_h[0][idx] = 0.0f;
        g_c[0][idx] = 0.0f;
    }
}

// ---------------- attention gate: x_att = softmax(tanh(x@Wa + hc@Ua + ba)@Va) * x
// 256 threads = 4 batch rows x 64 lanes. Grid 128.
__global__ void __launch_bounds__(256) attn_kernel(const float* __restrict__ x,
                                                   const float* __restrict__ Wa,
                                                   const float* __restrict__ Ua,
                                                   const float* __restrict__ ba,
                                                   const float* __restrict__ Va,
                                                   int s, int pp) {
    const float* __restrict__ h_in = g_h[pp];
    const float* __restrict__ c_in = g_c[pp];

    const int row = threadIdx.x >> 6;   // 0..3
    const int d   = threadIdx.x & 63;   // 0..63
    const int b   = blockIdx.x * 4 + row;

    __shared__ float hc_s[4][2 * H];
    __shared__ float xr_s[4][D];
    __shared__ float pre_s[4][D];
    __shared__ float red_s[4][D];

    for (int k = d; k < 2 * H; k += 64)
        hc_s[row][k] = (k < H) ? h_in[b * H + k] : c_in[b * H + (k - H)];
    xr_s[row][d] = x[(b * SEQ + s) * D + d];
    __syncthreads();

    float acc = ba[d];
#pragma unroll 8
    for (int k = 0; k < D; k++)
        acc = fmaf(xr_s[row][k], Wa[k * D + d], acc);
#pragma unroll 8
    for (int k = 0; k < 2 * H; k++)
        acc = fmaf(hc_s[row][k], Ua[k * D + d], acc);
    pre_s[row][d] = tanhf(acc);
    __syncthreads();

    float a = 0.0f;
#pragma unroll 8
    for (int k = 0; k < D; k++)
        a = fmaf(pre_s[row][k], Va[k * D + d], a);

    // softmax over 64 lanes (2 warps -> smem tree reduce)
    red_s[row][d] = a;
    __syncthreads();
    for (int off = 32; off > 0; off >>= 1) {
        if (d < off) red_s[row][d] = fmaxf(red_s[row][d], red_s[row][d + off]);
        __syncthreads();
    }
    float m = red_s[row][0];
    __syncthreads();
    float e = expf(a - m);
    red_s[row][d] = e;
    __syncthreads();
    for (int off = 32; off > 0; off >>= 1) {
        if (d < off) red_s[row][d] += red_s[row][d + off];
        __syncthreads();
    }
    float inv = 1.0f / red_s[row][0];
    g_xatt[b * D + d] = e * inv * xr_s[row][d];
}

// ---------------- gates GEMM + fused LSTM cell update ----------------
// grid (8 col-tiles, 16 batch-tiles); CTA tile [32 x 256], K = 576, Kt = 32.
// thread (tx=tid&31, ty=tid>>5): rows ty*4..+3, cols {tx*4 + 128*j + 0..3}, j=0,1
// -> each thread owns 2 complete (i,f,g,o) quadruples per row => fused epilogue.
__global__ void __launch_bounds__(256) gates_kernel(int pp) {
    const float* __restrict__ h_in  = g_h[pp];
    const float* __restrict__ c_in  = g_c[pp];
    float* __restrict__ h_out = g_h[1 - pp];
    float* __restrict__ c_out = g_c[1 - pp];

    const int colbase = blockIdx.x * 256;
    const int bbase   = blockIdx.y * 32;

    __shared__ float As[32][33];    // [row][k] +1 pad
    __shared__ float Bs[32][256];   // [k][col]

    const int tid = threadIdx.x;
    const int tx  = tid & 31;
    const int ty  = tid >> 5;

    float acc[4][8];
#pragma unroll
    for (int r = 0; r < 4; r++)
#pragma unroll
        for (int c = 0; c < 8; c++) acc[r][c] = 0.0f;

    for (int kt = 0; kt < KDIM; kt += 32) {
        // load A tile 32x32 (x_att | h_in)
#pragma unroll
        for (int j = 0; j < 4; j++) {
            int e  = tid + j * 256;
            int r  = e >> 5;
            int kk = e & 31;
            int kg = kt + kk;
            float v = (kg < D) ? g_xatt[(bbase + r) * D + kg]
                               : h_in[(bbase + r) * H + (kg - D)];
            As[r][kk] = v;
        }
        // load B tile 32x256 (pre-transposed weights, coalesced over cols)
#pragma unroll 4
        for (int kk = 0; kk < 32; kk++)
            Bs[kk][tid] = g_W[(kt + kk) * G + colbase + tid];
        __syncthreads();

#pragma unroll
        for (int kk = 0; kk < 32; kk++) {
            float4 b0 = *reinterpret_cast<const float4*>(&Bs[kk][tx * 4]);
            float4 b1 = *reinterpret_cast<const float4*>(&Bs[kk][tx * 4 + 128]);
            float a0 = As[ty * 4 + 0][kk];
            float a1 = As[ty * 4 + 1][kk];
            float a2 = As[ty * 4 + 2][kk];
            float a3 = As[ty * 4 + 3][kk];
            acc[0][0] = fmaf(a0, b0.x, acc[0][0]); acc[0][1] = fmaf(a0, b0.y, acc[0][1]);
            acc[0][2] = fmaf(a0, b0.z, acc[0][2]); acc[0][3] = fmaf(a0, b0.w, acc[0][3]);
            acc[0][4] = fmaf(a0, b1.x, acc[0][4]); acc[0][5] = fmaf(a0, b1.y, acc[0][5]);
            acc[0][6] = fmaf(a0, b1.z, acc[0][6]); acc[0][7] = fmaf(a0, b1.w, acc[0][7]);
            acc[1][0] = fmaf(a1, b0.x, acc[1][0]); acc[1][1] = fmaf(a1, b0.y, acc[1][1]);
            acc[1][2] = fmaf(a1, b0.z, acc[1][2]); acc[1][3] = fmaf(a1, b0.w, acc[1][3]);
            acc[1][4] = fmaf(a1, b1.x, acc[1][4]); acc[1][5] = fmaf(a1, b1.y, acc[1][5]);
            acc[1][6] = fmaf(a1, b1.z, acc[1][6]); acc[1][7] = fmaf(a1, b1.w, acc[1][7]);
            acc[2][0] = fmaf(a2, b0.x, acc[2][0]); acc[2][1] = fmaf(a2, b0.y, acc[2][1]);
            acc[2][2] = fmaf(a2, b0.z, acc[2][2]); acc[2][3] = fmaf(a2, b0.w, acc[2][3]);
            acc[2][4] = fmaf(a2, b1.x, acc[2][4]); acc[2][5] = fmaf(a2, b1.y, acc[2][5]);
            acc[2][6] = fmaf(a2, b1.z, acc[2][6]); acc[2][7] = fmaf(a2, b1.w, acc[2][7]);
            acc[3][0] = fmaf(a3, b0.x, acc[3][0]); acc[3][1] = fmaf(a3, b0.y, acc[3][1]);
            acc[3][2] = fmaf(a3, b0.z, acc[3][2]); acc[3][3] = fmaf(a3, b0.w, acc[3][3]);
            acc[3][4] = fmaf(a3, b1.x, acc[3][4]); acc[3][5] = fmaf(a3, b1.y, acc[3][5]);
            acc[3][6] = fmaf(a3, b1.z, acc[3][6]); acc[3][7] = fmaf(a3, b1.w, acc[3][7]);
        }
        __syncthreads();
    }

    // fused LSTM epilogue: cols are (i,f,g,o) quadruples at g' = hh*4+t
#pragma unroll
    for (int r = 0; r < 4; r++) {
        const int b = bbase + ty * 4 + r;
#pragma unroll
        for (int j = 0; j < 2; j++) {
            int gp0 = colbase + tx * 4 + j * 128;
            int hh  = gp0 >> 2;
            float iv = acc[r][j * 4 + 0] + g_bias[gp0 + 0];
            float fv = acc[r][j * 4 + 1] + g_bias[gp0 + 1];
            float gv = acc[r][j * 4 + 2] + g_bias[gp0 + 2];
            float ov = acc[r][j * 4 + 3] + g_bias[gp0 + 3];
            float co = c_in[b * H + hh];
            float cn = sigf(fv) * co + sigf(iv) * tanhf(gv);
            float hn = sigf(ov) * tanhf(cn);
            c_out[b * H + hh] = cn;
            h_out[b * H + hh] = hn;
        }
    }
}

// ---------------- final FC: y = h_T @ fc_w.T + fc_b ----------------
__global__ void __launch_bounds__(256) fc_kernel(const float* __restrict__ fc_w,
                                                 const float* __restrict__ fc_b,
                                                 float* __restrict__ out) {
    __shared__ float hs[H];
    const int b = blockIdx.x;
    const float* __restrict__ h_fin = g_h[0];  // SEQ even -> final state in buffer 0
    for (int k = threadIdx.x; k < H; k += blockDim.x) hs[k] = h_fin[b * H + k];
    __syncthreads();

    const int w    = threadIdx.x >> 5;   // warp 0..7
    const int lane = threadIdx.x & 31;
#pragma unroll
    for (int j = 0; j < 3; j++) {
        int o = w * 3 + j;               // 8 warps x 3 = 24 outputs
        float acc = 0.0f;
#pragma unroll 4
        for (int k = lane; k < H; k += 32)
            acc = fmaf(hs[k], fc_w[o * H + k], acc);
#pragma unroll
        for (int off = 16; off > 0; off >>= 1)
            acc += __shfl_xor_sync(0xffffffffu, acc, off);
        if (lane == 0) out[b * PRED + o] = acc + fc_b[o];
    }
}

// ---------------- launch ----------------
extern "C" void kernel_launch(void* const* d_in, const int* in_sizes, int n_in,
                              void* d_out, int out_size) {
    const float* x    = (const float*)d_in[0];
    const float* Wa   = (const float*)d_in[1];
    const float* Ua   = (const float*)d_in[2];
    const float* ba   = (const float*)d_in[3];
    const float* Va   = (const float*)d_in[4];
    const float* W_ih = (const float*)d_in[5];
    const float* W_hh = (const float*)d_in[6];
    const float* b_ih = (const float*)d_in[7];
    const float* b_hh = (const float*)d_in[8];
    const float* fc_w = (const float*)d_in[9];
    const float* fc_b = (const float*)d_in[10];
    float* out = (float*)d_out;

    init_kernel<<<512, 256>>>(W_ih, W_hh, b_ih, b_hh);

    for (int s = 0; s < SEQ; s++) {
        int pp = s & 1;
        attn_kernel<<<128, 256>>>(x, Wa, Ua, ba, Va, s, pp);
        gates_kernel<<<dim3(8, 16), 256>>>(pp);
    }

    fc_kernel<<<BATCH, 256>>>(fc_w, fc_b, out);
}

// round 3
// speedup vs baseline: 1.1995x; 1.1995x over previous
#include <cuda_runtime.h>
#include <math.h>

#define BATCH 512
#define SEQ   256
#define D     64
#define H     512
#define G     2048   /* 4*H gate columns */
#define KDIM  576    /* D + H */
#define PRED  24

// ---------------- device scratch (no allocations allowed) ----------------
__device__ float g_W[KDIM * G];     // combined weights, [k][g'] with g' = hh*4 + t
__device__ float g_bias[G];         // permuted combined bias
__device__ float g_h[2][BATCH * H]; // ping-pong hidden state
__device__ float g_c[2][BATCH * H]; // ping-pong cell state
__device__ float g_xatt[BATCH * D]; // attention-gated input for current step
__device__ float g_xw[SEQ * BATCH * D]; // precomputed x@Wa + ba, [s][b][d]

__device__ __forceinline__ float sigf(float x) { return 1.0f / (1.0f + expf(-x)); }

// ---------------- init: transpose/permute weights, zero state ----------------
__global__ void __launch_bounds__(256) init_kernel(const float* __restrict__ W_ih,
                                                   const float* __restrict__ W_hh,
                                                   const float* __restrict__ b_ih,
                                                   const float* __restrict__ b_hh) {
    const int stride = gridDim.x * blockDim.x;
    const int tid0 = blockIdx.x * blockDim.x + threadIdx.x;

    for (int idx = tid0; idx < KDIM * G; idx += stride) {
        int k  = idx / G;
        int gp = idx - k * G;
        int hh = gp >> 2;
        int t  = gp & 3;
        int g  = t * H + hh;
        float v = (k < D) ? W_ih[g * D + k] : W_hh[g * H + (k - D)];
        g_W[idx] = v;
    }
    for (int idx = tid0; idx < G; idx += stride) {
        int hh = idx >> 2;
        int t  = idx & 3;
        int g  = t * H + hh;
        g_bias[idx] = b_ih[g] + b_hh[g];
    }
    for (int idx = tid0; idx < BATCH * H; idx += stride) {
        g_h[0][idx] = 0.0f;
        g_c[0][idx] = 0.0f;
    }
}

// ---------------- one-time: xw[s][b][d] = x[b][s][:] @ Wa + ba ----------------
// grid 4096 CTAs: each handles 32 consecutive (s*BATCH+b) rows (same s).
__global__ void __launch_bounds__(256) xw_kernel(const float* __restrict__ x,
                                                 const float* __restrict__ Wa,
                                                 const float* __restrict__ ba) {
    __shared__ float Wa_s[D * D];   // [k][d]
    __shared__ float xs[32][D];

    const int tid = threadIdx.x;
    const int r0  = blockIdx.x * 32;        // row = s*BATCH + b
    const int s   = r0 / BATCH;
    const int b0  = r0 % BATCH;             // 32 rows stay within one s (512%32==0)

    // load Wa (4096 floats) via float4
    {
        const float4* src = (const float4*)Wa;
        float4* dst = (float4*)Wa_s;
#pragma unroll
        for (int j = 0; j < 4; j++) dst[tid + j * 256] = src[tid + j * 256];
    }
    // load 32 x-rows
#pragma unroll
    for (int j = 0; j < 8; j++) {
        int idx = tid + j * 256;
        int i = idx >> 6, dd = idx & 63;
        xs[i][dd] = x[((b0 + i) * SEQ + s) * D + dd];
    }
    __syncthreads();

    const int d   = tid & 63;
    const int grp = tid >> 6;   // 0..3, each handles 8 rows
    float bv = ba[d];
    float acc[8];
#pragma unroll
    for (int i = 0; i < 8; i++) acc[i] = bv;

#pragma unroll
    for (int k = 0; k < D; k += 4) {
        float w0 = Wa_s[(k + 0) * D + d];
        float w1 = Wa_s[(k + 1) * D + d];
        float w2 = Wa_s[(k + 2) * D + d];
        float w3 = Wa_s[(k + 3) * D + d];
#pragma unroll
        for (int i = 0; i < 8; i++) {
            float4 xv = *(const float4*)&xs[grp * 8 + i][k];
            acc[i] = fmaf(xv.x, w0, acc[i]);
            acc[i] = fmaf(xv.y, w1, acc[i]);
            acc[i] = fmaf(xv.z, w2, acc[i]);
            acc[i] = fmaf(xv.w, w3, acc[i]);
        }
    }
#pragma unroll
    for (int i = 0; i < 8; i++)
        g_xw[(r0 + grp * 8 + i) * D + d] = acc[i];
}

// ---------------- attention gate (SMEM-staged) ----------------
// x_att = softmax(tanh(xw + hc@Ua)@Va) * x.  grid 128, block 256 = 4 rows x 64 d.
__global__ void __launch_bounds__(256) attn_kernel(const float* __restrict__ x,
                                                   const float* __restrict__ Ua,
                                                   const float* __restrict__ Va,
                                                   int s, int pp) {
    const float* __restrict__ h_in = g_h[pp];
    const float* __restrict__ c_in = g_c[pp];

    const int tid  = threadIdx.x;
    const int row  = tid >> 6;    // 0..3
    const int d    = tid & 63;
    const int wid  = tid >> 5;    // 0..7
    const int lane = tid & 31;
    const int b    = blockIdx.x * 4 + row;

    __shared__ float hc_s[4][2 * H];   // 16KB
    __shared__ float U_s[64 * D];      // 16KB, Ua k-tile, later reused for Va
    __shared__ float pre_s[4][D];
    __shared__ float wred[8];
    __shared__ float wred2[8];

    // load hc (coalesced over k)
#pragma unroll
    for (int j = 0; j < 16; j++) {
        int idx = tid + j * 256;
        int r = idx >> 10, k = idx & 1023;
        int bb = blockIdx.x * 4 + r;
        hc_s[r][k] = (k < H) ? h_in[bb * H + k] : c_in[bb * H + (k - H)];
    }

    float acc = g_xw[((long)s * BATCH + b) * D + d];   // xw + ba already folded

    for (int kt = 0; kt < 2 * H; kt += 64) {
        __syncthreads();   // protect U_s reuse
        {
            const float4* src = (const float4*)(Ua + kt * D);
            float4* dst = (float4*)U_s;
#pragma unroll
            for (int j = 0; j < 4; j++) dst[tid + j * 256] = src[tid + j * 256];
        }
        __syncthreads();
#pragma unroll
        for (int k = 0; k < 64; k += 4) {
            float4 hv = *(const float4*)&hc_s[row][kt + k];
            acc = fmaf(hv.x, U_s[(k + 0) * D + d], acc);
            acc = fmaf(hv.y, U_s[(k + 1) * D + d], acc);
            acc = fmaf(hv.z, U_s[(k + 2) * D + d], acc);
            acc = fmaf(hv.w, U_s[(k + 3) * D + d], acc);
        }
    }

    // stage Va into U_s, write tanh(acc)
    __syncthreads();
    {
        const float4* src = (const float4*)Va;
        float4* dst = (float4*)U_s;
#pragma unroll
        for (int j = 0; j < 4; j++) dst[tid + j * 256] = src[tid + j * 256];
    }
    pre_s[row][d] = tanhf(acc);
    __syncthreads();

    float a = 0.0f;
#pragma unroll
    for (int k = 0; k < D; k += 4) {
        float4 pv = *(const float4*)&pre_s[row][k];
        a = fmaf(pv.x, U_s[(k + 0) * D + d], a);
        a = fmaf(pv.y, U_s[(k + 1) * D + d], a);
        a = fmaf(pv.z, U_s[(k + 2) * D + d], a);
        a = fmaf(pv.w, U_s[(k + 3) * D + d], a);
    }

    // softmax over 64 lanes (= 2 warps per row): shfl + cross-warp combine
    float m = a;
#pragma unroll
    for (int off = 16; off > 0; off >>= 1)
        m = fmaxf(m, __shfl_xor_sync(0xffffffffu, m, off));
    if (lane == 0) wred[wid] = m;
    __syncthreads();
    m = fmaxf(wred[row * 2], wred[row * 2 + 1]);

    float e = expf(a - m);
    float ssum = e;
#pragma unroll
    for (int off = 16; off > 0; off >>= 1)
        ssum += __shfl_xor_sync(0xffffffffu, ssum, off);
    if (lane == 0) wred2[wid] = ssum;
    __syncthreads();
    ssum = wred2[row * 2] + wred2[row * 2 + 1];

    float xv = x[(b * SEQ + s) * D + d];
    g_xatt[b * D + d] = (e / ssum) * xv;
}

// ---------------- gates GEMM + fused LSTM cell update ----------------
__global__ void __launch_bounds__(256) gates_kernel(int pp) {
    const float* __restrict__ h_in  = g_h[pp];
    const float* __restrict__ c_in  = g_c[pp];
    float* __restrict__ h_out = g_h[1 - pp];
    float* __restrict__ c_out = g_c[1 - pp];

    const int colbase = blockIdx.x * 256;
    const int bbase   = blockIdx.y * 32;

    __shared__ float As[32][33];
    __shared__ float Bs[32][256];

    const int tid = threadIdx.x;
    const int tx  = tid & 31;
    const int ty  = tid >> 5;

    float acc[4][8];
#pragma unroll
    for (int r = 0; r < 4; r++)
#pragma unroll
        for (int c = 0; c < 8; c++) acc[r][c] = 0.0f;

    for (int kt = 0; kt < KDIM; kt += 32) {
#pragma unroll
        for (int j = 0; j < 4; j++) {
            int e  = tid + j * 256;
            int r  = e >> 5;
            int kk = e & 31;
            int kg = kt + kk;
            float v = (kg < D) ? g_xatt[(bbase + r) * D + kg]
                               : h_in[(bbase + r) * H + (kg - D)];
            As[r][kk] = v;
        }
#pragma unroll 4
        for (int kk = 0; kk < 32; kk++)
            Bs[kk][tid] = g_W[(kt + kk) * G + colbase + tid];
        __syncthreads();

#pragma unroll
        for (int kk = 0; kk < 32; kk++) {
            float4 b0 = *reinterpret_cast<const float4*>(&Bs[kk][tx * 4]);
            float4 b1 = *reinterpret_cast<const float4*>(&Bs[kk][tx * 4 + 128]);
            float a0 = As[ty * 4 + 0][kk];
            float a1 = As[ty * 4 + 1][kk];
            float a2 = As[ty * 4 + 2][kk];
            float a3 = As[ty * 4 + 3][kk];
            acc[0][0] = fmaf(a0, b0.x, acc[0][0]); acc[0][1] = fmaf(a0, b0.y, acc[0][1]);
            acc[0][2] = fmaf(a0, b0.z, acc[0][2]); acc[0][3] = fmaf(a0, b0.w, acc[0][3]);
            acc[0][4] = fmaf(a0, b1.x, acc[0][4]); acc[0][5] = fmaf(a0, b1.y, acc[0][5]);
            acc[0][6] = fmaf(a0, b1.z, acc[0][6]); acc[0][7] = fmaf(a0, b1.w, acc[0][7]);
            acc[1][0] = fmaf(a1, b0.x, acc[1][0]); acc[1][1] = fmaf(a1, b0.y, acc[1][1]);
            acc[1][2] = fmaf(a1, b0.z, acc[1][2]); acc[1][3] = fmaf(a1, b0.w, acc[1][3]);
            acc[1][4] = fmaf(a1, b1.x, acc[1][4]); acc[1][5] = fmaf(a1, b1.y, acc[1][5]);
            acc[1][6] = fmaf(a1, b1.z, acc[1][6]); acc[1][7] = fmaf(a1, b1.w, acc[1][7]);
            acc[2][0] = fmaf(a2, b0.x, acc[2][0]); acc[2][1] = fmaf(a2, b0.y, acc[2][1]);
            acc[2][2] = fmaf(a2, b0.z, acc[2][2]); acc[2][3] = fmaf(a2, b0.w, acc[2][3]);
            acc[2][4] = fmaf(a2, b1.x, acc[2][4]); acc[2][5] = fmaf(a2, b1.y, acc[2][5]);
            acc[2][6] = fmaf(a2, b1.z, acc[2][6]); acc[2][7] = fmaf(a2, b1.w, acc[2][7]);
            acc[3][0] = fmaf(a3, b0.x, acc[3][0]); acc[3][1] = fmaf(a3, b0.y, acc[3][1]);
            acc[3][2] = fmaf(a3, b0.z, acc[3][2]); acc[3][3] = fmaf(a3, b0.w, acc[3][3]);
            acc[3][4] = fmaf(a3, b1.x, acc[3][4]); acc[3][5] = fmaf(a3, b1.y, acc[3][5]);
            acc[3][6] = fmaf(a3, b1.z, acc[3][6]); acc[3][7] = fmaf(a3, b1.w, acc[3][7]);
        }
        __syncthreads();
    }

#pragma unroll
    for (int r = 0; r < 4; r++) {
        const int b = bbase + ty * 4 + r;
#pragma unroll
        for (int j = 0; j < 2; j++) {
            int gp0 = colbase + tx * 4 + j * 128;
            int hh  = gp0 >> 2;
            float iv = acc[r][j * 4 + 0] + g_bias[gp0 + 0];
            float fv = acc[r][j * 4 + 1] + g_bias[gp0 + 1];
            float gv = acc[r][j * 4 + 2] + g_bias[gp0 + 2];
            float ov = acc[r][j * 4 + 3] + g_bias[gp0 + 3];
            float co = c_in[b * H + hh];
            float cn = sigf(fv) * co + sigf(iv) * tanhf(gv);
            float hn = sigf(ov) * tanhf(cn);
            c_out[b * H + hh] = cn;
            h_out[b * H + hh] = hn;
        }
    }
}

// ---------------- final FC ----------------
__global__ void __launch_bounds__(256) fc_kernel(const float* __restrict__ fc_w,
                                                 const float* __restrict__ fc_b,
                                                 float* __restrict__ out) {
    __shared__ float hs[H];
    const int b = blockIdx.x;
    const float* __restrict__ h_fin = g_h[0];  // SEQ even -> final state in buffer 0
    for (int k = threadIdx.x; k < H; k += blockDim.x) hs[k] = h_fin[b * H + k];
    __syncthreads();

    const int w    = threadIdx.x >> 5;
    const int lane = threadIdx.x & 31;
#pragma unroll
    for (int j = 0; j < 3; j++) {
        int o = w * 3 + j;
        float acc = 0.0f;
#pragma unroll 4
        for (int k = lane; k < H; k += 32)
            acc = fmaf(hs[k], fc_w[o * H + k], acc);
#pragma unroll
        for (int off = 16; off > 0; off >>= 1)
            acc += __shfl_xor_sync(0xffffffffu, acc, off);
        if (lane == 0) out[b * PRED + o] = acc + fc_b[o];
    }
}

// ---------------- launch ----------------
extern "C" void kernel_launch(void* const* d_in, const int* in_sizes, int n_in,
                              void* d_out, int out_size) {
    const float* x    = (const float*)d_in[0];
    const float* Wa   = (const float*)d_in[1];
    const float* Ua   = (const float*)d_in[2];
    const float* ba   = (const float*)d_in[3];
    const float* Va   = (const float*)d_in[4];
    const float* W_ih = (const float*)d_in[5];
    const float* W_hh = (const float*)d_in[6];
    const float* b_ih = (const float*)d_in[7];
    const float* b_hh = (const float*)d_in[8];
    const float* fc_w = (const float*)d_in[9];
    const float* fc_b = (const float*)d_in[10];
    float* out = (float*)d_out;

    init_kernel<<<512, 256>>>(W_ih, W_hh, b_ih, b_hh);
    xw_kernel<<<(BATCH * SEQ) / 32, 256>>>(x, Wa, ba);

    for (int s = 0; s < SEQ; s++) {
        int pp = s & 1;
        attn_kernel<<<128, 256>>>(x, Ua, Va, s, pp);
        gates_kernel<<<dim3(8, 16), 256>>>(pp);
    }

    fc_kernel<<<BATCH, 256>>>(fc_w, fc_b, out);
}

// round 4
// speedup vs baseline: 1.5359x; 1.2804x over previous
#include <cuda_runtime.h>
#include <math.h>
#include <stdint.h>

#define BATCH 512
#define SEQ   256
#define D     64
#define H     512
#define G     2048   /* 4*H gate columns */
#define KDIM  576    /* D + H */
#define PRED  24

// ---------------- device scratch (no allocations allowed) ----------------
__device__ uint32_t g_W32[KDIM * G];  // tf32 weights, [k][g'] with g' = hh*4 + t
__device__ float g_bias[G];           // permuted combined bias
__device__ float g_h[2][BATCH * H];   // ping-pong hidden state
__device__ float g_c[2][BATCH * H];   // ping-pong cell state
__device__ float g_xatt[BATCH * D];   // attention-gated input for current step
__device__ float g_xw[SEQ * BATCH * D]; // precomputed x@Wa + ba, [s][b][d]

__device__ __forceinline__ float sigf(float x) { return 1.0f / (1.0f + expf(-x)); }

__device__ __forceinline__ uint32_t f2tf32(float f) {
    uint32_t r;
    asm("cvt.rna.tf32.f32 %0, %1;" : "=r"(r) : "f"(f));
    return r;
}

__device__ __forceinline__ void mma_tf32(float* d, const uint32_t* a,
                                         uint32_t b0, uint32_t b1) {
    asm volatile(
        "mma.sync.aligned.m16n8k8.row.col.f32.tf32.tf32.f32 "
        "{%0,%1,%2,%3}, {%4,%5,%6,%7}, {%8,%9}, {%0,%1,%2,%3};"
        : "+f"(d[0]), "+f"(d[1]), "+f"(d[2]), "+f"(d[3])
        : "r"(a[0]), "r"(a[1]), "r"(a[2]), "r"(a[3]), "r"(b0), "r"(b1));
}

// ---------------- init: permute+convert weights, zero state ----------------
__global__ void __launch_bounds__(256) init_kernel(const float* __restrict__ W_ih,
                                                   const float* __restrict__ W_hh,
                                                   const float* __restrict__ b_ih,
                                                   const float* __restrict__ b_hh) {
    const int stride = gridDim.x * blockDim.x;
    const int tid0 = blockIdx.x * blockDim.x + threadIdx.x;

    for (int idx = tid0; idx < KDIM * G; idx += stride) {
        int k  = idx / G;
        int gp = idx - k * G;
        int hh = gp >> 2;
        int t  = gp & 3;
        int g  = t * H + hh;
        float v = (k < D) ? W_ih[g * D + k] : W_hh[g * H + (k - D)];
        g_W32[idx] = f2tf32(v);
    }
    for (int idx = tid0; idx < G; idx += stride) {
        int hh = idx >> 2;
        int t  = idx & 3;
        int g  = t * H + hh;
        g_bias[idx] = b_ih[g] + b_hh[g];
    }
    for (int idx = tid0; idx < BATCH * H; idx += stride) {
        g_h[0][idx] = 0.0f;
        g_c[0][idx] = 0.0f;
    }
}

// ---------------- one-time: xw[s][b][d] = x[b][s][:] @ Wa + ba ----------------
__global__ void __launch_bounds__(256) xw_kernel(const float* __restrict__ x,
                                                 const float* __restrict__ Wa,
                                                 const float* __restrict__ ba) {
    __shared__ float Wa_s[D * D];
    __shared__ float xs[32][D];

    const int tid = threadIdx.x;
    const int r0  = blockIdx.x * 32;
    const int s   = r0 / BATCH;
    const int b0  = r0 % BATCH;

    {
        const float4* src = (const float4*)Wa;
        float4* dst = (float4*)Wa_s;
#pragma unroll
        for (int j = 0; j < 4; j++) dst[tid + j * 256] = src[tid + j * 256];
    }
#pragma unroll
    for (int j = 0; j < 8; j++) {
        int idx = tid + j * 256;
        int i = idx >> 6, dd = idx & 63;
        xs[i][dd] = x[((b0 + i) * SEQ + s) * D + dd];
    }
    __syncthreads();

    const int d   = tid & 63;
    const int grp = tid >> 6;
    float bv = ba[d];
    float acc[8];
#pragma unroll
    for (int i = 0; i < 8; i++) acc[i] = bv;

#pragma unroll
    for (int k = 0; k < D; k += 4) {
        float w0 = Wa_s[(k + 0) * D + d];
        float w1 = Wa_s[(k + 1) * D + d];
        float w2 = Wa_s[(k + 2) * D + d];
        float w3 = Wa_s[(k + 3) * D + d];
#pragma unroll
        for (int i = 0; i < 8; i++) {
            float4 xv = *(const float4*)&xs[grp * 8 + i][k];
            acc[i] = fmaf(xv.x, w0, acc[i]);
            acc[i] = fmaf(xv.y, w1, acc[i]);
            acc[i] = fmaf(xv.z, w2, acc[i]);
            acc[i] = fmaf(xv.w, w3, acc[i]);
        }
    }
#pragma unroll
    for (int i = 0; i < 8; i++)
        g_xw[(r0 + grp * 8 + i) * D + d] = acc[i];
}

// ---------------- attention gate (SMEM-staged) ----------------
__global__ void __launch_bounds__(256) attn_kernel(const float* __restrict__ x,
                                                   const float* __restrict__ Ua,
                                                   const float* __restrict__ Va,
                                                   int s, int pp) {
    const float* __restrict__ h_in = g_h[pp];
    const float* __restrict__ c_in = g_c[pp];

    const int tid  = threadIdx.x;
    const int row  = tid >> 6;
    const int d    = tid & 63;
    const int wid  = tid >> 5;
    const int lane = tid & 31;
    const int b    = blockIdx.x * 4 + row;

    __shared__ float hc_s[4][2 * H];
    __shared__ float U_s[64 * D];
    __shared__ float pre_s[4][D];
    __shared__ float wred[8];
    __shared__ float wred2[8];

#pragma unroll
    for (int j = 0; j < 16; j++) {
        int idx = tid + j * 256;
        int r = idx >> 10, k = idx & 1023;
        int bb = blockIdx.x * 4 + r;
        hc_s[r][k] = (k < H) ? h_in[bb * H + k] : c_in[bb * H + (k - H)];
    }

    float acc = g_xw[((long)s * BATCH + b) * D + d];

    for (int kt = 0; kt < 2 * H; kt += 64) {
        __syncthreads();
        {
            const float4* src = (const float4*)(Ua + kt * D);
            float4* dst = (float4*)U_s;
#pragma unroll
            for (int j = 0; j < 4; j++) dst[tid + j * 256] = src[tid + j * 256];
        }
        __syncthreads();
#pragma unroll
        for (int k = 0; k < 64; k += 4) {
            float4 hv = *(const float4*)&hc_s[row][kt + k];
            acc = fmaf(hv.x, U_s[(k + 0) * D + d], acc);
            acc = fmaf(hv.y, U_s[(k + 1) * D + d], acc);
            acc = fmaf(hv.z, U_s[(k + 2) * D + d], acc);
            acc = fmaf(hv.w, U_s[(k + 3) * D + d], acc);
        }
    }

    __syncthreads();
    {
        const float4* src = (const float4*)Va;
        float4* dst = (float4*)U_s;
#pragma unroll
        for (int j = 0; j < 4; j++) dst[tid + j * 256] = src[tid + j * 256];
    }
    pre_s[row][d] = tanhf(acc);
    __syncthreads();

    float a = 0.0f;
#pragma unroll
    for (int k = 0; k < D; k += 4) {
        float4 pv = *(const float4*)&pre_s[row][k];
        a = fmaf(pv.x, U_s[(k + 0) * D + d], a);
        a = fmaf(pv.y, U_s[(k + 1) * D + d], a);
        a = fmaf(pv.z, U_s[(k + 2) * D + d], a);
        a = fmaf(pv.w, U_s[(k + 3) * D + d], a);
    }

    float m = a;
#pragma unroll
    for (int off = 16; off > 0; off >>= 1)
        m = fmaxf(m, __shfl_xor_sync(0xffffffffu, m, off));
    if (lane == 0) wred[wid] = m;
    __syncthreads();
    m = fmaxf(wred[row * 2], wred[row * 2 + 1]);

    float e = expf(a - m);
    float ssum = e;
#pragma unroll
    for (int off = 16; off > 0; off >>= 1)
        ssum += __shfl_xor_sync(0xffffffffu, ssum, off);
    if (lane == 0) wred2[wid] = ssum;
    __syncthreads();
    ssum = wred2[row * 2] + wred2[row * 2 + 1];

    float xv = x[(b * SEQ + s) * D + d];
    g_xatt[b * D + d] = (e / ssum) * xv;
}

// ---------------- gates GEMM (tf32 mma.sync) + fused LSTM cell ----------------
// grid (32 col-tiles x 8 batch-tiles), 128 threads = 4 warps (2x2 of 32x32).
// smem strides 72 (== 8 mod 32) -> conflict-free fragment loads.
#define ASTRIDE 72
__global__ void __launch_bounds__(128) gates_kernel(int pp) {
    const float* __restrict__ h_in  = g_h[pp];
    const float* __restrict__ c_in  = g_c[pp];
    float* __restrict__ h_out = g_h[1 - pp];
    float* __restrict__ c_out = g_c[1 - pp];

    const int colbase = blockIdx.x * 64;   // g' column base
    const int bbase   = blockIdx.y * 64;   // batch row base

    __shared__ __align__(16) uint32_t sh[2 * 32 * ASTRIDE];
    uint32_t* As = sh;                 // [k][row]  32 x 72
    uint32_t* Bs = sh + 32 * ASTRIDE;  // [k][col]  32 x 72
    float*    Cs = (float*)sh;         // epilogue: 64 x 68 (17408B <= 18432B)

    const int tid  = threadIdx.x;
    const int lane = tid & 31;
    const int wid  = tid >> 5;
    const int gq   = lane >> 2;        // groupID 0..7
    const int tig  = lane & 3;         // threadID_in_group
    const int r0   = (wid >> 1) * 32;  // warp row base
    const int n0c  = (wid & 1) * 32;   // warp col base

    // A-load mapping: each thread loads 16 consecutive k of one row
    const int arow = tid >> 1;
    const int akh  = (tid & 1) * 16;
    // B-load mapping: each thread loads 16 consecutive cols of one k
    const int bkk = tid >> 2;
    const int bn0 = (tid & 3) * 16;

    float acc[2][4][4];
#pragma unroll
    for (int rf = 0; rf < 2; rf++)
#pragma unroll
        for (int j = 0; j < 4; j++)
#pragma unroll
            for (int q = 0; q < 4; q++) acc[rf][j][q] = 0.0f;

    for (int kt = 0; kt < KDIM; kt += 32) {
        // global -> regs (before barrier: overlap latency)
        float av[16];
        {
            const float* src = (kt < D) ? &g_xatt[(bbase + arow) * D + kt + akh]
                                        : &h_in[(bbase + arow) * H + (kt - D) + akh];
#pragma unroll
            for (int j = 0; j < 4; j++) {
                float4 v = *(const float4*)(src + j * 4);
                av[j * 4 + 0] = v.x; av[j * 4 + 1] = v.y;
                av[j * 4 + 2] = v.z; av[j * 4 + 3] = v.w;
            }
        }
        uint4 bv[4];
        {
            const uint4* wsrc = (const uint4*)&g_W32[(kt + bkk) * G + colbase + bn0];
#pragma unroll
            for (int j = 0; j < 4; j++) bv[j] = wsrc[j];
        }

        __syncthreads();   // previous iteration's fragment loads complete
#pragma unroll
        for (int i = 0; i < 16; i++)
            As[(akh + i) * ASTRIDE + arow] = f2tf32(av[i]);
        {
            uint4* dst = (uint4*)&Bs[bkk * ASTRIDE + bn0];
#pragma unroll
            for (int j = 0; j < 4; j++) dst[j] = bv[j];
        }
        __syncthreads();

#pragma unroll
        for (int kf = 0; kf < 4; kf++) {
            const int kb = kf * 8;
            uint32_t a[2][4];
#pragma unroll
            for (int rf = 0; rf < 2; rf++) {
                const int rb = r0 + rf * 16;
                a[rf][0] = As[(kb + tig) * ASTRIDE + rb + gq];
                a[rf][1] = As[(kb + tig) * ASTRIDE + rb + gq + 8];
                a[rf][2] = As[(kb + tig + 4) * ASTRIDE + rb + gq];
                a[rf][3] = As[(kb + tig + 4) * ASTRIDE + rb + gq + 8];
            }
#pragma unroll
            for (int j = 0; j < 4; j++) {
                uint32_t b0 = Bs[(kb + tig) * ASTRIDE + n0c + j * 8 + gq];
                uint32_t b1 = Bs[(kb + tig + 4) * ASTRIDE + n0c + j * 8 + gq];
                mma_tf32(acc[0][j], a[0], b0, b1);
                mma_tf32(acc[1][j], a[1], b0, b1);
            }
        }
    }

    // dump gate accs to smem for clean quadruple epilogue
    __syncthreads();
#pragma unroll
    for (int rf = 0; rf < 2; rf++) {
#pragma unroll
        for (int j = 0; j < 4; j++) {
            const int row = r0 + rf * 16 + gq;
            const int col = n0c + j * 8 + 2 * tig;
            *(float2*)&Cs[row * 68 + col]       = make_float2(acc[rf][j][0], acc[rf][j][1]);
            *(float2*)&Cs[(row + 8) * 68 + col] = make_float2(acc[rf][j][2], acc[rf][j][3]);
        }
    }
    __syncthreads();

    // cell update: thread -> (hh group, 8 rows)
    const int hhi   = tid & 15;          // local hidden index (16 per CTA)
    const int rbase = (tid >> 4) * 8;    // 8 rows each
    const int hh    = (colbase >> 2) + hhi;
    const float4 b4 = *(const float4*)&g_bias[colbase + hhi * 4];

#pragma unroll
    for (int r = 0; r < 8; r++) {
        const int row = rbase + r;
        const int b   = bbase + row;
        float4 gv = *(const float4*)&Cs[row * 68 + hhi * 4];
        float iv = gv.x + b4.x;
        float fv = gv.y + b4.y;
        float gg = gv.z + b4.z;
        float ov = gv.w + b4.w;
        float co = c_in[b * H + hh];
        float cn = sigf(fv) * co + sigf(iv) * tanhf(gg);
        float hn = sigf(ov) * tanhf(cn);
        c_out[b * H + hh] = cn;
        h_out[b * H + hh] = hn;
    }
}

// ---------------- final FC ----------------
__global__ void __launch_bounds__(256) fc_kernel(const float* __restrict__ fc_w,
                                                 const float* __restrict__ fc_b,
                                                 float* __restrict__ out) {
    __shared__ float hs[H];
    const int b = blockIdx.x;
    const float* __restrict__ h_fin = g_h[0];  // SEQ even -> final state in buffer 0
    for (int k = threadIdx.x; k < H; k += blockDim.x) hs[k] = h_fin[b * H + k];
    __syncthreads();

    const int w    = threadIdx.x >> 5;
    const int lane = threadIdx.x & 31;
#pragma unroll
    for (int j = 0; j < 3; j++) {
        int o = w * 3 + j;
        float acc = 0.0f;
#pragma unroll 4
        for (int k = lane; k < H; k += 32)
            acc = fmaf(hs[k], fc_w[o * H + k], acc);
#pragma unroll
        for (int off = 16; off > 0; off >>= 1)
            acc += __shfl_xor_sync(0xffffffffu, acc, off);
        if (lane == 0) out[b * PRED + o] = acc + fc_b[o];
    }
}

// ---------------- launch ----------------
extern "C" void kernel_launch(void* const* d_in, const int* in_sizes, int n_in,
                              void* d_out, int out_size) {
    const float* x    = (const float*)d_in[0];
    const float* Wa   = (const float*)d_in[1];
    const float* Ua   = (const float*)d_in[2];
    const float* ba   = (const float*)d_in[3];
    const float* Va   = (const float*)d_in[4];
    const float* W_ih = (const float*)d_in[5];
    const float* W_hh = (const float*)d_in[6];
    const float* b_ih = (const float*)d_in[7];
    const float* b_hh = (const float*)d_in[8];
    const float* fc_w = (const float*)d_in[9];
    const float* fc_b = (const float*)d_in[10];
    float* out = (float*)d_out;

    init_kernel<<<512, 256>>>(W_ih, W_hh, b_ih, b_hh);
    xw_kernel<<<(BATCH * SEQ) / 32, 256>>>(x, Wa, ba);

    for (int s = 0; s < SEQ; s++) {
        int pp = s & 1;
        attn_kernel<<<128, 256>>>(x, Ua, Va, s, pp);
        gates_kernel<<<dim3(32, 8), 128>>>(pp);
    }

    fc_kernel<<<BATCH, 256>>>(fc_w, fc_b, out);
}

// round 5
// speedup vs baseline: 2.5716x; 1.6743x over previous
#include <cuda_runtime.h>
#include <math.h>
#include <stdint.h>

#define BATCH 512
#define SEQ   256
#define D     64
#define H     512
#define G     2048   /* 4*H gate columns */
#define KDIM  576    /* D + H */
#define PRED  24

#define NCTA  128
#define NTHR  256
#define BSTRIDE 68            /* words per k-row of weight smem  */
#define ASTRIDE 136           /* words per k-row of A slab (128 rows + pad) */
#define CSTRIDE 68

#define SMEM_BW_BYTES   (KDIM * BSTRIDE * 4)          /* 156672 */
#define SMEM_SCRATCH    (128 * CSTRIDE * 4)           /* 34816  */
#define SMEM_TOTAL      (SMEM_BW_BYTES + SMEM_SCRATCH)

// ---------------- device scratch (no allocations allowed) ----------------
__device__ uint32_t g_W32[KDIM * G];  // tf32 weights, [k][g'] with g' = hh*4 + t
__device__ float g_bias[G];           // permuted combined bias
__device__ float g_h[2][BATCH * H];   // ping-pong hidden state
__device__ float g_c[2][BATCH * H];   // ping-pong cell state
__device__ float g_xatt[BATCH * D];   // attention-gated input for current step
__device__ float g_xw[SEQ * BATCH * D]; // precomputed x@Wa + ba, [s][b][d]

__device__ unsigned g_bar_cnt;            // zero-init; invariant: returns to 0
__device__ volatile unsigned g_bar_gen;   // monotonically increasing epoch

__device__ __forceinline__ float sigf(float x) { return 1.0f / (1.0f + expf(-x)); }

__device__ __forceinline__ uint32_t f2tf32(float f) {
    uint32_t r;
    asm("cvt.rna.tf32.f32 %0, %1;" : "=r"(r) : "f"(f));
    return r;
}

__device__ __forceinline__ void mma_tf32(float* d, const uint32_t* a,
                                         uint32_t b0, uint32_t b1) {
    asm volatile(
        "mma.sync.aligned.m16n8k8.row.col.f32.tf32.tf32.f32 "
        "{%0,%1,%2,%3}, {%4,%5,%6,%7}, {%8,%9}, {%0,%1,%2,%3};"
        : "+f"(d[0]), "+f"(d[1]), "+f"(d[2]), "+f"(d[3])
        : "r"(a[0]), "r"(a[1]), "r"(a[2]), "r"(a[3]), "r"(b0), "r"(b1));
}

// all-CTA barrier; safe because all NCTA CTAs are co-resident (128 <= 148 SMs,
// 1 CTA/SM by smem). Epoch-based: state returns to (cnt=0) after every barrier.
__device__ __forceinline__ void grid_barrier() {
    __syncthreads();
    if (threadIdx.x == 0) {
        __threadfence();
        unsigned gen = g_bar_gen;
        if (atomicAdd(&g_bar_cnt, 1u) == NCTA - 1) {
            g_bar_cnt = 0;
            __threadfence();
            g_bar_gen = gen + 1;
        } else {
            while (g_bar_gen == gen) { }
        }
        __threadfence();
    }
    __syncthreads();
}

// ---------------- init: permute+convert weights, zero state ----------------
__global__ void __launch_bounds__(256) init_kernel(const float* __restrict__ W_ih,
                                                   const float* __restrict__ W_hh,
                                                   const float* __restrict__ b_ih,
                                                   const float* __restrict__ b_hh) {
    const int stride = gridDim.x * blockDim.x;
    const int tid0 = blockIdx.x * blockDim.x + threadIdx.x;

    for (int idx = tid0; idx < KDIM * G; idx += stride) {
        int k  = idx / G;
        int gp = idx - k * G;
        int hh = gp >> 2;
        int t  = gp & 3;
        int g  = t * H + hh;
        float v = (k < D) ? W_ih[g * D + k] : W_hh[g * H + (k - D)];
        g_W32[idx] = f2tf32(v);
    }
    for (int idx = tid0; idx < G; idx += stride) {
        int hh = idx >> 2;
        int t  = idx & 3;
        int g  = t * H + hh;
        g_bias[idx] = b_ih[g] + b_hh[g];
    }
    for (int idx = tid0; idx < BATCH * H; idx += stride) {
        g_h[0][idx] = 0.0f;
        g_c[0][idx] = 0.0f;
    }
}

// ---------------- one-time: xw[s][b][d] = x[b][s][:] @ Wa + ba ----------------
__global__ void __launch_bounds__(256) xw_kernel(const float* __restrict__ x,
                                                 const float* __restrict__ Wa,
                                                 const float* __restrict__ ba) {
    __shared__ float Wa_s[D * D];
    __shared__ float xs[32][D];

    const int tid = threadIdx.x;
    const int r0  = blockIdx.x * 32;
    const int s   = r0 / BATCH;
    const int b0  = r0 % BATCH;

    {
        const float4* src = (const float4*)Wa;
        float4* dst = (float4*)Wa_s;
#pragma unroll
        for (int j = 0; j < 4; j++) dst[tid + j * 256] = src[tid + j * 256];
    }
#pragma unroll
    for (int j = 0; j < 8; j++) {
        int idx = tid + j * 256;
        int i = idx >> 6, dd = idx & 63;
        xs[i][dd] = x[((b0 + i) * SEQ + s) * D + dd];
    }
    __syncthreads();

    const int d   = tid & 63;
    const int grp = tid >> 6;
    float bv = ba[d];
    float acc[8];
#pragma unroll
    for (int i = 0; i < 8; i++) acc[i] = bv;

#pragma unroll
    for (int k = 0; k < D; k += 4) {
        float w0 = Wa_s[(k + 0) * D + d];
        float w1 = Wa_s[(k + 1) * D + d];
        float w2 = Wa_s[(k + 2) * D + d];
        float w3 = Wa_s[(k + 3) * D + d];
#pragma unroll
        for (int i = 0; i < 8; i++) {
            float4 xv = *(const float4*)&xs[grp * 8 + i][k];
            acc[i] = fmaf(xv.x, w0, acc[i]);
            acc[i] = fmaf(xv.y, w1, acc[i]);
            acc[i] = fmaf(xv.z, w2, acc[i]);
            acc[i] = fmaf(xv.w, w3, acc[i]);
        }
    }
#pragma unroll
    for (int i = 0; i < 8; i++)
        g_xw[(r0 + grp * 8 + i) * D + d] = acc[i];
}

// ---------------- persistent kernel: 256 steps of attn + gates ----------------
__global__ void __launch_bounds__(NTHR, 1) persist_kernel(const float* __restrict__ x,
                                                          const float* __restrict__ Ua,
                                                          const float* __restrict__ Va) {
    extern __shared__ __align__(16) char smem[];
    uint32_t* Bw = (uint32_t*)smem;                 // 576 x 68 weight slice (tf32)
    char* scratch = smem + SMEM_BW_BYTES;

    const int tid = threadIdx.x;
    const int cta = blockIdx.x;
    const int ct  = cta & 31;           // coltile 0..31
    const int bt  = cta >> 5;           // batch group 0..3
    const int colbase = ct * 64;        // g' base
    const int bbase   = bt * 128;       // batch base for gates

    // ---- load this CTA's weight slice into smem (once) ----
    for (int i = tid; i < KDIM * 16; i += NTHR) {
        int k = i >> 4, c4 = (i & 15) * 4;
        *(uint4*)&Bw[k * BSTRIDE + c4] = *(const uint4*)&g_W32[k * G + colbase + c4];
    }

    // thread/warp mapping for mma
    const int lane = tid & 31;
    const int wid  = tid >> 5;
    const int gq   = lane >> 2;
    const int tig  = lane & 3;
    const int r0   = (wid >> 1) * 32;   // warp row base (0/32/64/96)
    const int n0   = (wid & 1) * 32;    // warp col base (0/32)

    // attn scratch views
    float (*hc_s)[2 * H] = (float (*)[2 * H])scratch;       // 16KB
    float* U_s   = (float*)(scratch + 16384);               // 16KB
    float* pre_s = (float*)(scratch + 32768);               // 4x64
    float* wred  = (float*)(scratch + 33792);               // 8
    float* wred2 = wred + 8;
    // gates scratch views (overlap attn region; phases separated by barriers)
    uint32_t* As = (uint32_t*)scratch;                      // 32 x 136 words
    float*    Cs = (float*)scratch;                         // 128 x 68 floats

    // A-stage mapping
    const int arow = tid >> 1;          // 0..127
    const int akh  = (tid & 1) * 16;    // 0 / 16
    // epilogue mapping
    const int hhi   = tid & 15;
    const int rbase = (tid >> 4) * 8;
    const int hh    = (colbase >> 2) + hhi;

    const int arow_d = tid >> 6;        // attn row 0..3
    const int ad     = tid & 63;        // attn feature
    const int ab     = cta * 4 + arow_d;

    int pp = 0;
    grid_barrier();   // weight slices loaded before anyone proceeds (also syncs smem)

    for (int s = 0; s < SEQ; s++) {
        const float* __restrict__ h_in = g_h[pp];
        const float* __restrict__ c_in = g_c[pp];
        float* __restrict__ h_out = g_h[1 - pp];
        float* __restrict__ c_out = g_c[1 - pp];

        // ===================== attn phase (4 rows per CTA) =====================
        {
#pragma unroll
            for (int j = 0; j < 16; j++) {
                int idx = tid + j * 256;
                int r = idx >> 10, k = idx & 1023;
                int bb = cta * 4 + r;
                hc_s[r][k] = (k < H) ? h_in[bb * H + k] : c_in[bb * H + (k - H)];
            }

            float acc = g_xw[(s * BATCH + ab) * D + ad];

            for (int kt2 = 0; kt2 < 2 * H; kt2 += 64) {
                __syncthreads();
                {
                    const float4* src = (const float4*)(Ua + kt2 * D);
                    float4* dst = (float4*)U_s;
#pragma unroll
                    for (int j = 0; j < 4; j++) dst[tid + j * 256] = src[tid + j * 256];
                }
                __syncthreads();
#pragma unroll
                for (int k = 0; k < 64; k += 4) {
                    float4 hv = *(const float4*)&hc_s[arow_d][kt2 + k];
                    acc = fmaf(hv.x, U_s[(k + 0) * D + ad], acc);
                    acc = fmaf(hv.y, U_s[(k + 1) * D + ad], acc);
                    acc = fmaf(hv.z, U_s[(k + 2) * D + ad], acc);
                    acc = fmaf(hv.w, U_s[(k + 3) * D + ad], acc);
                }
            }

            __syncthreads();
            {
                const float4* src = (const float4*)Va;
                float4* dst = (float4*)U_s;
#pragma unroll
                for (int j = 0; j < 4; j++) dst[tid + j * 256] = src[tid + j * 256];
            }
            pre_s[arow_d * D + ad] = tanhf(acc);
            __syncthreads();

            float a = 0.0f;
#pragma unroll
            for (int k = 0; k < D; k += 4) {
                float4 pv = *(const float4*)&pre_s[arow_d * D + k];
                a = fmaf(pv.x, U_s[(k + 0) * D + ad], a);
                a = fmaf(pv.y, U_s[(k + 1) * D + ad], a);
                a = fmaf(pv.z, U_s[(k + 2) * D + ad], a);
                a = fmaf(pv.w, U_s[(k + 3) * D + ad], a);
            }

            float m = a;
#pragma unroll
            for (int off = 16; off > 0; off >>= 1)
                m = fmaxf(m, __shfl_xor_sync(0xffffffffu, m, off));
            if (lane == 0) wred[wid] = m;
            __syncthreads();
            m = fmaxf(wred[arow_d * 2], wred[arow_d * 2 + 1]);

            float e = expf(a - m);
            float ssum = e;
#pragma unroll
            for (int off = 16; off > 0; off >>= 1)
                ssum += __shfl_xor_sync(0xffffffffu, ssum, off);
            if (lane == 0) wred2[wid] = ssum;
            __syncthreads();
            ssum = wred2[arow_d * 2] + wred2[arow_d * 2 + 1];

            float xv = x[(ab * SEQ + s) * D + ad];
            g_xatt[ab * D + ad] = (e / ssum) * xv;
        }

        grid_barrier();   // xatt visible to all

        // ===================== gates phase (128x64 tile) =====================
        {
            float acc[2][4][4];
#pragma unroll
            for (int rf = 0; rf < 2; rf++)
#pragma unroll
                for (int j = 0; j < 4; j++)
#pragma unroll
                    for (int q = 0; q < 4; q++) acc[rf][j][q] = 0.0f;

            float av[16];
            {   // prefetch slab 0
                const float* src = &g_xatt[(bbase + arow) * D + akh];
#pragma unroll
                for (int j = 0; j < 4; j++) {
                    float4 v = *(const float4*)(src + j * 4);
                    av[j * 4 + 0] = v.x; av[j * 4 + 1] = v.y;
                    av[j * 4 + 2] = v.z; av[j * 4 + 3] = v.w;
                }
            }

            for (int kt = 0; kt < KDIM; kt += 32) {
                __syncthreads();
#pragma unroll
                for (int i = 0; i < 16; i++)
                    As[(akh + i) * ASTRIDE + arow] = f2tf32(av[i]);
                __syncthreads();

                if (kt + 32 < KDIM) {   // prefetch next slab
                    int kn = kt + 32;
                    const float* src = (kn < D) ? &g_xatt[(bbase + arow) * D + kn + akh]
                                                : &h_in[(bbase + arow) * H + (kn - D) + akh];
#pragma unroll
                    for (int j = 0; j < 4; j++) {
                        float4 v = *(const float4*)(src + j * 4);
                        av[j * 4 + 0] = v.x; av[j * 4 + 1] = v.y;
                        av[j * 4 + 2] = v.z; av[j * 4 + 3] = v.w;
                    }
                }

#pragma unroll
                for (int kf = 0; kf < 4; kf++) {
                    const int kb = kf * 8;
                    uint32_t a[2][4];
#pragma unroll
                    for (int rf = 0; rf < 2; rf++) {
                        const int rb = r0 + rf * 16;
                        a[rf][0] = As[(kb + tig) * ASTRIDE + rb + gq];
                        a[rf][1] = As[(kb + tig) * ASTRIDE + rb + gq + 8];
                        a[rf][2] = As[(kb + tig + 4) * ASTRIDE + rb + gq];
                        a[rf][3] = As[(kb + tig + 4) * ASTRIDE + rb + gq + 8];
                    }
                    const int kg0 = (kt + kb + tig) * BSTRIDE;
                    const int kg1 = (kt + kb + tig + 4) * BSTRIDE;
#pragma unroll
                    for (int j = 0; j < 4; j++) {
                        uint32_t b0 = Bw[kg0 + n0 + j * 8 + gq];
                        uint32_t b1 = Bw[kg1 + n0 + j * 8 + gq];
                        mma_tf32(acc[0][j], a[0], b0, b1);
                        mma_tf32(acc[1][j], a[1], b0, b1);
                    }
                }
            }

            __syncthreads();
#pragma unroll
            for (int rf = 0; rf < 2; rf++) {
#pragma unroll
                for (int j = 0; j < 4; j++) {
                    const int row = r0 + rf * 16 + gq;
                    const int col = n0 + j * 8 + 2 * tig;
                    *(float2*)&Cs[row * CSTRIDE + col]       = make_float2(acc[rf][j][0], acc[rf][j][1]);
                    *(float2*)&Cs[(row + 8) * CSTRIDE + col] = make_float2(acc[rf][j][2], acc[rf][j][3]);
                }
            }
            __syncthreads();

            const float4 b4 = *(const float4*)&g_bias[colbase + hhi * 4];
#pragma unroll
            for (int r = 0; r < 8; r++) {
                const int row = rbase + r;
                const int b   = bbase + row;
                float4 gv = *(const float4*)&Cs[row * CSTRIDE + hhi * 4];
                float iv = gv.x + b4.x;
                float fv = gv.y + b4.y;
                float gg = gv.z + b4.z;
                float ov = gv.w + b4.w;
                float co = c_in[b * H + hh];
                float cn = sigf(fv) * co + sigf(iv) * tanhf(gg);
                float hn = sigf(ov) * tanhf(cn);
                c_out[b * H + hh] = cn;
                h_out[b * H + hh] = hn;
            }
        }

        grid_barrier();   // h/c visible to all
        pp ^= 1;
    }
}

// ---------------- final FC ----------------
__global__ void __launch_bounds__(256) fc_kernel(const float* __restrict__ fc_w,
                                                 const float* __restrict__ fc_b,
                                                 float* __restrict__ out) {
    __shared__ float hs[H];
    const int b = blockIdx.x;
    const float* __restrict__ h_fin = g_h[0];  // SEQ even -> final state in buffer 0
    for (int k = threadIdx.x; k < H; k += blockDim.x) hs[k] = h_fin[b * H + k];
    __syncthreads();

    const int w    = threadIdx.x >> 5;
    const int lane = threadIdx.x & 31;
#pragma unroll
    for (int j = 0; j < 3; j++) {
        int o = w * 3 + j;
        float acc = 0.0f;
#pragma unroll 4
        for (int k = lane; k < H; k += 32)
            acc = fmaf(hs[k], fc_w[o * H + k], acc);
#pragma unroll
        for (int off = 16; off > 0; off >>= 1)
            acc += __shfl_xor_sync(0xffffffffu, acc, off);
        if (lane == 0) out[b * PRED + o] = acc + fc_b[o];
    }
}

// ---------------- launch ----------------
extern "C" void kernel_launch(void* const* d_in, const int* in_sizes, int n_in,
                              void* d_out, int out_size) {
    const float* x    = (const float*)d_in[0];
    const float* Wa   = (const float*)d_in[1];
    const float* Ua   = (const float*)d_in[2];
    const float* ba   = (const float*)d_in[3];
    const float* Va   = (const float*)d_in[4];
    const float* W_ih = (const float*)d_in[5];
    const float* W_hh = (const float*)d_in[6];
    const float* b_ih = (const float*)d_in[7];
    const float* b_hh = (const float*)d_in[8];
    const float* fc_w = (const float*)d_in[9];
    const float* fc_b = (const float*)d_in[10];
    float* out = (float*)d_out;

    cudaFuncSetAttribute(persist_kernel,
                         cudaFuncAttributeMaxDynamicSharedMemorySize, SMEM_TOTAL);

    init_kernel<<<512, 256>>>(W_ih, W_hh, b_ih, b_hh);
    xw_kernel<<<(BATCH * SEQ) / 32, 256>>>(x, Wa, ba);
    persist_kernel<<<NCTA, NTHR, SMEM_TOTAL>>>(x, Ua, Va);
    fc_kernel<<<BATCH, 256>>>(fc_w, fc_b, out);
}

// round 8
// speedup vs baseline: 3.3137x; 1.2886x over previous
#include <cuda_runtime.h>
#include <cuda_fp16.h>
#include <math.h>
#include <stdint.h>

#define BATCH 512
#define SEQ   256
#define D     64
#define H     512
#define G     2048
#define KDIM  576
#define PRED  24

#define NCTA  128
#define NTHR  256

// ---- smem layout (bytes). B first, then A. ----
// row stride = 296 words = 592 halves (576 data + 16 pad); 296 % 32 == 8 -> conflict-free frags
#define SWW    296
#define SM_B   0
#define SM_B_BYTES (64 * SWW * 4)            /* 75776  */
#define SM_A   SM_B_BYTES
#define SM_A_BYTES (128 * SWW * 4)           /* 151552 */
#define SMEM_TOTAL (SM_A + SM_A_BYTES)       /* 227328 */

// ---------------- device scratch ----------------
__device__ __half g_W16[KDIM * G];   // fp16 weights, [k][g'], g' = hh*4 + t
__device__ float g_bias[G];
__device__ float g_h[2][BATCH * H];
__device__ float g_c[2][BATCH * H];
__device__ float g_xatt[BATCH * D];
__device__ float g_xw[SEQ * BATCH * D];

__device__ unsigned g_bar_cnt;
__device__ volatile unsigned g_bar_gen;

__device__ __forceinline__ float sigf(float x) { return 1.0f / (1.0f + expf(-x)); }

// k-interleave: pair index pc (k/2) -> word within row
__device__ __forceinline__ int kword(int pc) {
    int grp = pc >> 3, cg = pc & 7;
    return grp * 8 + (cg & 3) * 2 + (cg >> 2);
}

__device__ __forceinline__ void mma_fp16(float* d, uint32_t a0, uint32_t a1,
                                         uint32_t a2, uint32_t a3,
                                         uint32_t b0, uint32_t b1) {
    asm volatile(
        "mma.sync.aligned.m16n8k16.row.col.f32.f16.f16.f32 "
        "{%0,%1,%2,%3}, {%4,%5,%6,%7}, {%8,%9}, {%0,%1,%2,%3};"
        : "+f"(d[0]), "+f"(d[1]), "+f"(d[2]), "+f"(d[3])
        : "r"(a0), "r"(a1), "r"(a2), "r"(a3), "r"(b0), "r"(b1));
}

__device__ __forceinline__ void grid_barrier() {
    __syncthreads();
    if (threadIdx.x == 0) {
        __threadfence();
        unsigned gen = g_bar_gen;
        if (atomicAdd(&g_bar_cnt, 1u) == NCTA - 1) {
            g_bar_cnt = 0;
            __threadfence();
            g_bar_gen = gen + 1;
        } else {
            while (g_bar_gen == gen) { }
        }
        __threadfence();
    }
    __syncthreads();
}

// ---------------- init: permute+convert weights, zero state ----------------
__global__ void __launch_bounds__(256) init_kernel(const float* __restrict__ W_ih,
                                                   const float* __restrict__ W_hh,
                                                   const float* __restrict__ b_ih,
                                                   const float* __restrict__ b_hh) {
    const int stride = gridDim.x * blockDim.x;
    const int tid0 = blockIdx.x * blockDim.x + threadIdx.x;
    for (int idx = tid0; idx < KDIM * G; idx += stride) {
        int k = idx / G, gp = idx - k * G;
        int hh = gp >> 2, t = gp & 3, g = t * H + hh;
        float v = (k < D) ? W_ih[g * D + k] : W_hh[g * H + (k - D)];
        g_W16[idx] = __float2half_rn(v);
    }
    for (int idx = tid0; idx < G; idx += stride) {
        int hh = idx >> 2, t = idx & 3, g = t * H + hh;
        g_bias[idx] = b_ih[g] + b_hh[g];
    }
    for (int idx = tid0; idx < BATCH * H; idx += stride) {
        g_h[0][idx] = 0.0f;
        g_c[0][idx] = 0.0f;
    }
}

// ---------------- one-time xw = x@Wa + ba ----------------
__global__ void __launch_bounds__(256) xw_kernel(const float* __restrict__ x,
                                                 const float* __restrict__ Wa,
                                                 const float* __restrict__ ba) {
    __shared__ float Wa_s[D * D];
    __shared__ float xs[32][D];
    const int tid = threadIdx.x;
    const int r0 = blockIdx.x * 32;
    const int s = r0 / BATCH, b0 = r0 % BATCH;
    {
        const float4* src = (const float4*)Wa; float4* dst = (float4*)Wa_s;
#pragma unroll
        for (int j = 0; j < 4; j++) dst[tid + j * 256] = src[tid + j * 256];
    }
#pragma unroll
    for (int j = 0; j < 8; j++) {
        int idx = tid + j * 256; int i = idx >> 6, dd = idx & 63;
        xs[i][dd] = x[((b0 + i) * SEQ + s) * D + dd];
    }
    __syncthreads();
    const int d = tid & 63, grp = tid >> 6;
    float bv = ba[d], acc[8];
#pragma unroll
    for (int i = 0; i < 8; i++) acc[i] = bv;
#pragma unroll
    for (int k = 0; k < D; k += 4) {
        float w0 = Wa_s[k * D + d], w1 = Wa_s[(k + 1) * D + d];
        float w2 = Wa_s[(k + 2) * D + d], w3 = Wa_s[(k + 3) * D + d];
#pragma unroll
        for (int i = 0; i < 8; i++) {
            float4 xv = *(const float4*)&xs[grp * 8 + i][k];
            acc[i] = fmaf(xv.x, w0, acc[i]); acc[i] = fmaf(xv.y, w1, acc[i]);
            acc[i] = fmaf(xv.z, w2, acc[i]); acc[i] = fmaf(xv.w, w3, acc[i]);
        }
    }
#pragma unroll
    for (int i = 0; i < 8; i++) g_xw[(r0 + grp * 8 + i) * D + d] = acc[i];
}

// ---------------- persistent kernel ----------------
__global__ void __launch_bounds__(NTHR, 1)
persist_kernel(const float* __restrict__ x, const float* __restrict__ Ua,
               const float* __restrict__ Va) {
    extern __shared__ __align__(16) char smem[];
    const int tid = threadIdx.x;
    const int cta = blockIdx.x;
    const int ct = cta & 31, bt = cta >> 5;
    const int colbase = ct * 64, bbase = bt * 128;
    const int lane = tid & 31, wid = tid >> 5;

    // ---- load fp16 weight slice into interleaved B smem (once) ----
    {
        __half* Bh = (__half*)(smem + SM_B);
        for (int idx = tid; idx < 64 * KDIM; idx += NTHR) {
            int k = idx >> 6, n = idx & 63;
            __half w = g_W16[k * G + colbase + n];
            Bh[n * (SWW * 2) + kword(k >> 1) * 2 + (k & 1)] = w;
        }
    }

    // attn scratch views (inside A region; phases barrier-separated)
    float (*hc_s)[2 * H] = (float (*)[2 * H])(smem + SM_A);
    float* U_s   = (float*)(smem + SM_A + 16384);
    float* pre_s = (float*)(smem + SM_A + 32768);
    float* wred  = (float*)(smem + SM_A + 33792);
    float* wred2 = wred + 8;
    float* Cs    = (float*)(smem + SM_A);        // epilogue scratch 128x68

    const int arow_d = tid >> 6, ad = tid & 63, ab = cta * 4 + arow_d;

    // mma warp mapping: 4 row-groups x 2 col-groups
    const int mbase = (wid & 3) * 32;
    const int nbase = (wid >> 2) * 32;
    const int fr = lane >> 2;          // fragment row 0..7
    const int fc = (lane & 3) * 2;     // fragment word offset (k-pair*2)

    // cell-update mapping
    const int hhi   = tid & 15;
    const int rbase = (tid >> 4) * 8;
    const int hh    = (colbase >> 2) + hhi;

    int pp = 0;
    grid_barrier();   // weights staged everywhere

    for (int s = 0; s < SEQ; s++) {
        const float* __restrict__ h_in = g_h[pp];
        const float* __restrict__ c_in = g_c[pp];
        float* __restrict__ h_out = g_h[1 - pp];
        float* __restrict__ c_out = g_c[1 - pp];

        // ===================== attn phase (4 rows per CTA) =====================
        {
#pragma unroll
            for (int j = 0; j < 16; j++) {
                int idx = tid + j * 256;
                int r = idx >> 10, k = idx & 1023;
                int bb = cta * 4 + r;
                hc_s[r][k] = (k < H) ? h_in[bb * H + k] : c_in[bb * H + (k - H)];
            }

            float a0 = g_xw[(s * BATCH + ab) * D + ad];
            float a1 = 0.0f, a2 = 0.0f, a3 = 0.0f;

            for (int kt2 = 0; kt2 < 2 * H; kt2 += 64) {
                __syncthreads();
                {
                    const float4* src = (const float4*)(Ua + kt2 * D);
                    float4* dst = (float4*)U_s;
#pragma unroll
                    for (int j = 0; j < 4; j++) dst[tid + j * 256] = src[tid + j * 256];
                }
                __syncthreads();
#pragma unroll
                for (int k = 0; k < 64; k += 4) {
                    float4 hv = *(const float4*)&hc_s[arow_d][kt2 + k];
                    a0 = fmaf(hv.x, U_s[(k + 0) * D + ad], a0);
                    a1 = fmaf(hv.y, U_s[(k + 1) * D + ad], a1);
                    a2 = fmaf(hv.z, U_s[(k + 2) * D + ad], a2);
                    a3 = fmaf(hv.w, U_s[(k + 3) * D + ad], a3);
                }
            }
            float acc = (a0 + a1) + (a2 + a3);

            __syncthreads();
            {
                const float4* src = (const float4*)Va;
                float4* dst = (float4*)U_s;
#pragma unroll
                for (int j = 0; j < 4; j++) dst[tid + j * 256] = src[tid + j * 256];
            }
            pre_s[arow_d * D + ad] = tanhf(acc);
            __syncthreads();

            float v0 = 0.0f, v1 = 0.0f, v2 = 0.0f, v3 = 0.0f;
#pragma unroll
            for (int k = 0; k < D; k += 4) {
                float4 pv = *(const float4*)&pre_s[arow_d * D + k];
                v0 = fmaf(pv.x, U_s[(k + 0) * D + ad], v0);
                v1 = fmaf(pv.y, U_s[(k + 1) * D + ad], v1);
                v2 = fmaf(pv.z, U_s[(k + 2) * D + ad], v2);
                v3 = fmaf(pv.w, U_s[(k + 3) * D + ad], v3);
            }
            float av = (v0 + v1) + (v2 + v3);

            float m = av;
#pragma unroll
            for (int off = 16; off > 0; off >>= 1)
                m = fmaxf(m, __shfl_xor_sync(0xffffffffu, m, off));
            if (lane == 0) wred[wid] = m;
            __syncthreads();
            m = fmaxf(wred[arow_d * 2], wred[arow_d * 2 + 1]);

            float e = expf(av - m);
            float ssum = e;
#pragma unroll
            for (int off = 16; off > 0; off >>= 1)
                ssum += __shfl_xor_sync(0xffffffffu, ssum, off);
            if (lane == 0) wred2[wid] = ssum;
            __syncthreads();
            ssum = wred2[arow_d * 2] + wred2[arow_d * 2 + 1];

            float xv = x[(ab * SEQ + s) * D + ad];
            g_xatt[ab * D + ad] = (e / ssum) * xv;
        }

        grid_barrier();   // xatt visible to all (also frees attn smem)

        // ===================== stage A tile (fp16, interleaved) =====================
        {
            uint32_t* Aw = (uint32_t*)(smem + SM_A);
#pragma unroll 4
            for (int j = 0; j < 72; j++) {
                int idx = tid + j * 256;       // 0..18431 float4s
                int row = idx / 144;
                int kq  = idx - row * 144;     // float4 index; k = kq*4
                int k   = kq * 4;
                float4 v = (k < D)
                    ? *(const float4*)&g_xatt[(bbase + row) * D + k]
                    : *(const float4*)&h_in[(bbase + row) * H + (k - D)];
                __half2 p0 = __floats2half2_rn(v.x, v.y);
                __half2 p1 = __floats2half2_rn(v.z, v.w);
                uint32_t* Ar = Aw + row * SWW;
                Ar[kword(2 * kq)]     = *(uint32_t*)&p0;
                Ar[kword(2 * kq + 1)] = *(uint32_t*)&p1;
            }
        }
        __syncthreads();

        // ===================== mma mainloop =====================
        float acc[2][4][4];
#pragma unroll
        for (int mt = 0; mt < 2; mt++)
#pragma unroll
            for (int j = 0; j < 4; j++)
#pragma unroll
                for (int q = 0; q < 4; q++) acc[mt][j][q] = 0.0f;

        {
            const uint32_t* Aw = (const uint32_t*)(smem + SM_A);
            const uint32_t* Bw = (const uint32_t*)(smem + SM_B);
#pragma unroll 2
            for (int ks = 0; ks < 36; ks++) {
                const int kw = ks * 8 + fc;
                uint2 fa0 = *(const uint2*)&Aw[(mbase + fr) * SWW + kw];       // (a0,a2) mt0
                uint2 fa1 = *(const uint2*)&Aw[(mbase + fr + 8) * SWW + kw];   // (a1,a3) mt0
                uint2 fa2 = *(const uint2*)&Aw[(mbase + 16 + fr) * SWW + kw];  // mt1
                uint2 fa3 = *(const uint2*)&Aw[(mbase + 24 + fr) * SWW + kw];
#pragma unroll
                for (int j = 0; j < 4; j++) {
                    uint2 fb = *(const uint2*)&Bw[(nbase + j * 8 + fr) * SWW + kw];
                    mma_fp16(acc[0][j], fa0.x, fa1.x, fa0.y, fa1.y, fb.x, fb.y);
                    mma_fp16(acc[1][j], fa2.x, fa3.x, fa2.y, fa3.y, fb.x, fb.y);
                }
            }
        }
        __syncthreads();   // all warps done reading A before Cs overwrite

        // ---- dump gates to Cs, then fused cell update ----
#pragma unroll
        for (int mt = 0; mt < 2; mt++) {
#pragma unroll
            for (int j = 0; j < 4; j++) {
                const int row = mbase + mt * 16 + fr;
                const int col = nbase + j * 8 + fc;
                *(float2*)&Cs[row * 68 + col]       = make_float2(acc[mt][j][0], acc[mt][j][1]);
                *(float2*)&Cs[(row + 8) * 68 + col] = make_float2(acc[mt][j][2], acc[mt][j][3]);
            }
        }
        __syncthreads();

        {
            const float4 b4 = *(const float4*)&g_bias[colbase + hhi * 4];
#pragma unroll
            for (int r = 0; r < 8; r++) {
                const int row = rbase + r;
                const int b   = bbase + row;
                float4 gv = *(const float4*)&Cs[row * 68 + hhi * 4];
                float iv = gv.x + b4.x;
                float fv = gv.y + b4.y;
                float gg = gv.z + b4.z;
                float ov = gv.w + b4.w;
                float co = c_in[b * H + hh];
                float cn = sigf(fv) * co + sigf(iv) * tanhf(gg);
                float hn = sigf(ov) * tanhf(cn);
                c_out[b * H + hh] = cn;
                h_out[b * H + hh] = hn;
            }
        }

        grid_barrier();   // h/c visible to all
        pp ^= 1;
    }
}

// ---------------- final FC ----------------
__global__ void __launch_bounds__(256) fc_kernel(const float* __restrict__ fc_w,
                                                 const float* __restrict__ fc_b,
                                                 float* __restrict__ out) {
    __shared__ float hs[H];
    const int b = blockIdx.x;
    const float* __restrict__ h_fin = g_h[0];
    for (int k = threadIdx.x; k < H; k += blockDim.x) hs[k] = h_fin[b * H + k];
    __syncthreads();
    const int w = threadIdx.x >> 5, lane = threadIdx.x & 31;
#pragma unroll
    for (int j = 0; j < 3; j++) {
        int o = w * 3 + j;
        float acc = 0.0f;
#pragma unroll 4
        for (int k = lane; k < H; k += 32)
            acc = fmaf(hs[k], fc_w[o * H + k], acc);
#pragma unroll
        for (int off = 16; off > 0; off >>= 1)
            acc += __shfl_xor_sync(0xffffffffu, acc, off);
        if (lane == 0) out[b * PRED + o] = acc + fc_b[o];
    }
}

// ---------------- launch ----------------
extern "C" void kernel_launch(void* const* d_in, const int* in_sizes, int n_in,
                              void* d_out, int out_size) {
    const float* x    = (const float*)d_in[0];
    const float* Wa   = (const float*)d_in[1];
    const float* Ua   = (const float*)d_in[2];
    const float* ba   = (const float*)d_in[3];
    const float* Va   = (const float*)d_in[4];
    const float* W_ih = (const float*)d_in[5];
    const float* W_hh = (const float*)d_in[6];
    const float* b_ih = (const float*)d_in[7];
    const float* b_hh = (const float*)d_in[8];
    const float* fc_w = (const float*)d_in[9];
    const float* fc_b = (const float*)d_in[10];
    float* out = (float*)d_out;

    cudaFuncSetAttribute(persist_kernel,
                         cudaFuncAttributeMaxDynamicSharedMemorySize, SMEM_TOTAL);

    init_kernel<<<512, 256>>>(W_ih, W_hh, b_ih, b_hh);
    xw_kernel<<<(BATCH * SEQ) / 32, 256>>>(x, Wa, ba);
    persist_kernel<<<NCTA, NTHR, SMEM_TOTAL>>>(x, Ua, Va);
    fc_kernel<<<BATCH, 256>>>(fc_w, fc_b, out);
}